// round 7
// baseline (speedup 1.0000x reference)
#include <cuda_runtime.h>
#include <math.h>

#define NB   64
#define NC   512
#define NT   128
#define NV   1024
#define NQ   8
#define NIDX 255
#define NELEM (NB*NC*NT)
#define PLANE ((long long)NB*NT*NC)

// ---------------- device scratch ----------------
__device__ float g_zq[NELEM];
__device__ float g_zhat[NELEM];
__device__ float g_xd[NB*NC*NT];
__device__ float g_xs_a[2ll*NB*NT*NC];   // conv1 input tf32 splits [2][b][t][ci]
__device__ float g_xs_b[2ll*NB*NT*NC];   // conv2 input tf32 splits
__device__ float g_wsp[16ll*6*NC*NC];    // [qd][split*3+tap][co][ci] tf32 values
__device__ float g_cnorm[NQ*NV];
__device__ unsigned long long g_bestkey[NB*NT];
__device__ int   g_idxbuf[NB*NIDX];
__device__ int   g_counts[NV];
__device__ float g_partial[256];
__device__ float g_sums[3];

// ---------------- tf32 split helpers ----------------
__device__ __forceinline__ float tf32r(float x) {
    unsigned u;
    asm("cvt.rna.tf32.f32 %0, %1;" : "=r"(u) : "f"(x));
    return __uint_as_float(u);
}
__device__ __forceinline__ void split2(float x, float& hi, float& lo) {
    hi = tf32r(x);
    lo = tf32r(x - hi);
}

// ---------------- f32x2 helpers (quantize gemm) ----------------
__device__ __forceinline__ unsigned long long dup2(float x) {
    unsigned long long r;
    asm("mov.b64 %0, {%1, %1};" : "=l"(r) : "f"(x));
    return r;
}
__device__ __forceinline__ void fma2(unsigned long long& a, unsigned long long x, unsigned long long y) {
    asm("fma.rn.f32x2 %0, %1, %2, %0;" : "+l"(a) : "l"(x), "l"(y));
}
__device__ __forceinline__ float2 unpack2(unsigned long long v) {
    float2 f;
    asm("mov.b64 {%0, %1}, %2;" : "=f"(f.x), "=f"(f.y) : "l"(v));
    return f;
}

// ---------------- launch 0: init + cnorm + wsplit (fused) ----------------
__global__ void mega_init_kernel(const float* __restrict__ z, const float* __restrict__ cb,
                                 const float* __restrict__ pw) {
    int bx = blockIdx.x;
    int tid = threadIdx.x;
    if (bx < 2048) {
        long long stride = 2048ll * 256;
        long long t0 = (long long)bx * 256 + tid;
        for (long long i = t0; i < NELEM; i += stride) { g_zq[i] = z[i]; g_zhat[i] = 0.0f; }
        if (t0 < 3)   g_sums[t0] = 0.0f;
        if (t0 < NV)  g_counts[t0] = 0;
        if (t0 < 256) g_partial[t0] = 0.0f;
        if (t0 < NB*NT) g_bestkey[t0] = ~0ULL;
    } else if (bx < 2048 + 8192) {
        int row = bx - 2048;
        const float* p = cb + (long long)row * NC;
        float s = 0.0f;
        for (int c = tid; c < NC; c += 256) { float x = p[c]; s += x * x; }
        __shared__ float sh[8];
        for (int o = 16; o > 0; o >>= 1) s += __shfl_down_sync(0xffffffffu, s, o);
        if ((tid & 31) == 0) sh[tid >> 5] = s;
        __syncthreads();
        if (tid == 0) {
            float t = 0.0f;
            for (int w = 0; w < 8; w++) t += sh[w];
            g_cnorm[row] = t;
        }
    } else {
        long long i = (long long)(bx - 10240) * 256 + tid;
        if (i >= 16ll * NC * NC) return;
        int qd = (int)(i >> 18);
        int r  = (int)(i & (NC*NC - 1));
        int co = r >> 9, ci = r & 511;
        const float* src = pw + (((long long)qd * NC + co) * NC + ci) * 3;
        float* dst = g_wsp + (long long)qd * 6 * NC * NC;
#pragma unroll
        for (int k = 0; k < 3; k++) {
            float hi, lo;
            split2(src[k], hi, lo);
            dst[(long long)k * NC * NC + co * NC + ci]       = hi;
            dst[(long long)(3 + k) * NC * NC + co * NC + ci] = lo;
        }
    }
}

// ---------------- launch 1: fully fused s=1 quantize (mean + argmin + idx + hist) ----------------
__global__ __launch_bounds__(256) void quant_s1_kernel(const float* __restrict__ cb) {
    __shared__ float xs[512];
    __shared__ unsigned long long wbest[8];
    int b = blockIdx.x;
    int tid = threadIdx.x;
    int wp = tid >> 5, lane = tid & 31;

    for (int i = 0; i < 64; i++) {
        int row = wp * 64 + i;
        float4 v = ((const float4*)(g_zq + (long long)(b * NC + row) * NT))[lane];
        float s = v.x + v.y + v.z + v.w;
        for (int o = 16; o > 0; o >>= 1) s += __shfl_xor_sync(0xffffffffu, s, o);
        if (lane == 0) xs[row] = s * (1.0f / 128.0f);
    }
    __syncthreads();

    float bestv = INFINITY;
    int besti = 0;
    for (int cc = 0; cc < 128; cc++) {
        int code = wp * 128 + cc;
        const float* cbr = cb + (long long)code * 512;
        float d = 0.0f;
#pragma unroll
        for (int e = 0; e < 16; e++) d += xs[lane + 32 * e] * cbr[lane + 32 * e];
        for (int o = 16; o > 0; o >>= 1) d += __shfl_xor_sync(0xffffffffu, d, o);
        float sc = g_cnorm[code] - 2.0f * d;
        if (sc < bestv) { bestv = sc; besti = code; }
    }
    if (lane == 0) {
        unsigned u = __float_as_uint(bestv);
        u = (u & 0x80000000u) ? ~u : (u | 0x80000000u);
        wbest[wp] = ((unsigned long long)u << 32) | (unsigned)besti;
    }
    __syncthreads();
    if (tid == 0) {
        unsigned long long k = wbest[0];
        for (int i = 1; i < 8; i++) if (wbest[i] < k) k = wbest[i];
        int idx = (int)(k & 0xFFFFFFFFULL);
        g_idxbuf[b * NIDX] = idx;
        atomicAdd(&g_counts[idx], 1);
    }
}

// ---------------- downsample ----------------
__global__ void downsample_warp_kernel(int s, int slog) {
    int r = NT >> slog;
    int i = blockIdx.x * 8 + (threadIdx.x >> 5);
    int lane = threadIdx.x & 31;
    if (i >= NB * NC * s) return;
    int j  = i & (s - 1);
    int bc = i >> slog;
    const float* src = g_zq + (long long)bc * NT + j * r;
    float acc;
    if (r == 64) { float2 v = ((const float2*)src)[lane]; acc = v.x + v.y; }
    else         { acc = src[lane]; }
    for (int o = 16; o > 0; o >>= 1) acc += __shfl_xor_sync(0xffffffffu, acc, o);
    if (lane == 0) g_xd[i] = acc * (1.0f / (float)r);
}
__global__ void downsample_kernel(int s, int slog) {
    int total = NB * NC * s;
    int r = NT >> slog;
    int i = blockIdx.x * blockDim.x + threadIdx.x;
    if (i >= total) return;
    int j  = i & (s - 1);
    int bc = i >> slog;
    const float* src = g_zq + (long long)bc * NT + j * r;
    float acc = 0.0f;
    for (int k = 0; k < r; k++) acc += src[k];
    g_xd[i] = acc * (1.0f / (float)r);
}

// ---------------- quantize (s in 2..8) ----------------
template<int S>
__global__ __launch_bounds__(256) void quantize_small_kernel(const float* __restrict__ cb, int q) {
    __shared__ float xs[S][512];
    int b  = blockIdx.x;
    int c0 = blockIdx.y * 128;
    int tid = threadIdx.x;
    for (int e = tid; e < S * 512; e += 256) {
        int j = e >> 9, ch = e & 511;
        xs[j][ch] = g_xd[(b * 512 + ch) * S + j];
    }
    __syncthreads();
    int w = tid >> 5, lane = tid & 31;
    float bestv[S]; int besti[S];
#pragma unroll
    for (int j = 0; j < S; j++) { bestv[j] = INFINITY; besti[j] = 0; }
    for (int cc = 0; cc < 16; cc++) {
        int code = c0 + w * 16 + cc;
        const float* cbr = cb + (long long)code * 512;
        float cv[16];
#pragma unroll
        for (int e = 0; e < 16; e++) cv[e] = cbr[lane + 32 * e];
        float cn = g_cnorm[q * NV + code];
#pragma unroll
        for (int j = 0; j < S; j++) {
            float d = 0.0f;
#pragma unroll
            for (int e = 0; e < 16; e++) d += xs[j][lane + 32 * e] * cv[e];
            for (int o = 16; o > 0; o >>= 1) d += __shfl_xor_sync(0xffffffffu, d, o);
            float sc = cn - 2.0f * d;
            if (sc < bestv[j]) { bestv[j] = sc; besti[j] = code; }
        }
    }
    if (lane == 0) {
#pragma unroll
        for (int j = 0; j < S; j++) {
            unsigned u = __float_as_uint(bestv[j]);
            u = (u & 0x80000000u) ? ~u : (u | 0x80000000u);
            atomicMin(&g_bestkey[b * S + j], ((unsigned long long)u << 32) | (unsigned)besti[j]);
        }
    }
}

// ---------------- quantize (s>=16) ----------------
__global__ __launch_bounds__(256) void quantize_gemm_kernel(
    const float* __restrict__ cb, int q, int s, int slog)
{
    const int m0 = blockIdx.x * 64;
    const int n0 = blockIdx.y * 128;
    __shared__ float As[32][65];
    __shared__ float Bs[32][130];
    const int tid = threadIdx.x;
    const int ti = tid >> 4, tj = tid & 15;
    unsigned long long acc[4][4];
#pragma unroll
    for (int r = 0; r < 4; r++)
#pragma unroll
        for (int c = 0; c < 4; c++) acc[r][c] = 0ULL;
    for (int kc = 0; kc < NC; kc += 32) {
#pragma unroll
        for (int it = 0; it < 8; it++) {
            int e = tid + 256 * it;
            int m = e & 63, kk = e >> 6;
            int gm = m0 + m;
            int b = gm >> slog, j = gm & (s - 1);
            As[kk][m] = g_xd[(((long long)b * NC + (kc + kk)) << slog) + j];
        }
#pragma unroll
        for (int it = 0; it < 16; it++) {
            int e = tid + 256 * it;
            int kk = e & 31, n = e >> 5;
            Bs[kk][n] = cb[(long long)(n0 + n) * NC + kc + kk];
        }
        __syncthreads();
#pragma unroll 8
        for (int kk = 0; kk < 32; kk++) {
            unsigned long long a2[4], b2[4];
#pragma unroll
            for (int r = 0; r < 4; r++) a2[r] = dup2(As[kk][ti + 16 * r]);
#pragma unroll
            for (int c = 0; c < 4; c++) b2[c] = *(const unsigned long long*)&Bs[kk][2 * tj + 32 * c];
#pragma unroll
            for (int r = 0; r < 4; r++)
#pragma unroll
                for (int c = 0; c < 4; c++) fma2(acc[r][c], a2[r], b2[c]);
        }
        __syncthreads();
    }
    float bestv[4]; int besti[4];
#pragma unroll
    for (int r = 0; r < 4; r++) { bestv[r] = INFINITY; besti[r] = 0; }
#pragma unroll
    for (int c = 0; c < 4; c++) {
        int n = n0 + 2 * tj + 32 * c;
        float cn0 = g_cnorm[q * NV + n], cn1 = g_cnorm[q * NV + n + 1];
#pragma unroll
        for (int r = 0; r < 4; r++) {
            float2 dv = unpack2(acc[r][c]);
            float s0 = cn0 - 2.0f * dv.x, s1 = cn1 - 2.0f * dv.y;
            if (s0 < bestv[r]) { bestv[r] = s0; besti[r] = n; }
            if (s1 < bestv[r]) { bestv[r] = s1; besti[r] = n + 1; }
        }
    }
#pragma unroll
    for (int r = 0; r < 4; r++) {
        float v = bestv[r]; int ix = besti[r];
        for (int off = 8; off > 0; off >>= 1) {
            float ov = __shfl_down_sync(0xffffffffu, v, off, 16);
            int   oi = __shfl_down_sync(0xffffffffu, ix, off, 16);
            if (ov < v || (ov == v && oi < ix)) { v = ov; ix = oi; }
        }
        if (tj == 0) {
            unsigned u = __float_as_uint(v);
            u = (u & 0x80000000u) ? ~u : (u | 0x80000000u);
            atomicMin(&g_bestkey[m0 + ti + 16 * r], ((unsigned long long)u << 32) | (unsigned)ix);
        }
    }
}

// ---------------- extract idx + histogram (s>=2) ----------------
__global__ void post_quantize_kernel(int s, int slog) {
    int m = blockIdx.x * blockDim.x + threadIdx.x;
    if (m >= NB * s) return;
    int v = (int)(g_bestkey[m] & 0xFFFFFFFFULL);
    int b = m >> slog, j = m & (s - 1);
    g_idxbuf[b * NIDX + (s - 1) + j] = v;
    atomicAdd(&g_counts[v], 1);
}

// ---------------- upsample -> tf32 splits [2][b][t][ci] ----------------
__global__ void upsample_split_kernel(const float* __restrict__ cb, int s) {
    int b = blockIdx.x, t = blockIdx.y;
    float u = (t + 0.5f) * ((float)s / 128.0f) - 0.5f;
    float jf = floorf(u);
    float f = u - jf;
    int j0 = (int)jf, j1 = j0 + 1;
    if (j0 < 0) j0 = 0; if (j0 > s - 1) j0 = s - 1;
    if (j1 < 0) j1 = 0; if (j1 > s - 1) j1 = s - 1;
    int v0 = g_idxbuf[b * NIDX + (s - 1) + j0];
    int v1 = g_idxbuf[b * NIDX + (s - 1) + j1];
    const float* c0 = cb + (long long)v0 * NC;
    const float* c1 = cb + (long long)v1 * NC;
    float w1 = f, w0 = 1.0f - f;
    long long base = ((long long)(b * NT + t)) * NC;
    for (int c = threadIdx.x; c < NC; c += 128) {
        float val = w0 * c0[c] + w1 * c1[c];
        float hi, lo;
        split2(val, hi, lo);
        g_xs_a[base + c]         = hi;
        g_xs_a[base + c + PLANE] = lo;
    }
}

// ---------------- tf32 mma conv: 2 batches/CTA, 512 threads, W-prefetch double buffer ----------------
// smem floats: W 6*3072 @0; X 2 batches * 2 splits * 3120 @18432. total 30912 fl = 123648 B.
#define WOFF 0
#define XOFF 18432
#define CONV_SMEM (30912*4)
__global__ __launch_bounds__(512, 1) void conv_tc_kernel(
    const float* __restrict__ xs,   // [2][b][t][ci]
    const float* __restrict__ wsp,  // [6][co][ci] for this layer
    const float* __restrict__ bias,
    float* __restrict__ ys,
    const float* __restrict__ z, int fuse)
{
    extern __shared__ float sm[];
    const int tid = threadIdx.x, lane = tid & 31, wid = tid >> 5;
    const int h = wid >> 3, wh = wid & 7;
    const int cg = wh >> 2, tg = wh & 3;
    const int b0 = blockIdx.y * 2, co0 = blockIdx.x * 128;
    const int lq = lane >> 2, lr = lane & 3;

    float acc[4][4][4];
#pragma unroll
    for (int mt = 0; mt < 4; mt++)
#pragma unroll
        for (int nt = 0; nt < 4; nt++)
#pragma unroll
            for (int r = 0; r < 4; r++) acc[mt][nt][r] = 0.0f;

    float4 wpre[6];
#pragma unroll
    for (int i = 0; i < 6; i++) {
        int e = tid + 512 * i;
        int tile = e >> 9, r = e & 511, row = r >> 2, q = r & 3;
        wpre[i] = *(const float4*)(wsp + (long long)tile * (NC * NC)
                                   + (long long)(co0 + row) * NC + q * 4);
    }

    for (int ch = 0; ch < 32; ch++) {
        int ci0 = ch * 16;
        __syncthreads();
        // ---- store prefetched W ----
#pragma unroll
        for (int i = 0; i < 6; i++) {
            int e = tid + 512 * i;
            int tile = e >> 9, r = e & 511, row = r >> 2, q = r & 3;
            float* dst = sm + WOFF + tile * 3072 + row * 24;
            const float* pv = (const float*)&wpre[i];
#pragma unroll
            for (int li = 0; li < 4; li++) {
                int lc = q * 4 + li;
                int c = lc & 7;
                dst[((lc >> 3) << 3) + ((c & 3) << 1) + (c >> 2)] = pv[li];
            }
        }
        // ---- X: synchronous load + store (2 batches x 2 splits x 130 rows) ----
        for (int e = tid; e < 2080; e += 512) {
            int hb = (e >= 1040);
            int rem = e - hb * 1040;
            int sp = (rem >= 520);
            int r = rem - sp * 520;
            int row = r >> 2, q = r & 3;
            int t = row - 1;
            float4 v = make_float4(0.f, 0.f, 0.f, 0.f);
            if ((unsigned)t < 128u)
                v = *(const float4*)(xs + (long long)sp * PLANE
                                     + ((long long)((b0 + hb) * NT + t)) * NC + ci0 + q * 4);
            float* dst = sm + XOFF + hb * 6240 + sp * 3120 + row * 24;
            const float* pv = (const float*)&v;
#pragma unroll
            for (int li = 0; li < 4; li++) {
                int lc = q * 4 + li;
                int c = lc & 7;
                dst[((lc >> 3) << 3) + ((c & 3) << 1) + (c >> 2)] = pv[li];
            }
        }
        __syncthreads();
        // ---- prefetch next chunk's W (hidden behind mma) ----
        if (ch < 31) {
            int ci1 = ci0 + 16;
#pragma unroll
            for (int i = 0; i < 6; i++) {
                int e = tid + 512 * i;
                int tile = e >> 9, r = e & 511, row = r >> 2, q = r & 3;
                wpre[i] = *(const float4*)(wsp + (long long)tile * (NC * NC)
                                           + (long long)(co0 + row) * NC + ci1 + q * 4);
            }
        }
        // ---- mma: 3 terms (whi,xhi), (whi,xlo), (wlo,xhi) ----
#pragma unroll
        for (int wa = 0; wa < 2; wa++) {
            const int nxb = (wa == 0) ? 2 : 1;
            for (int tap = 0; tap < 3; tap++) {
                const float* Wt = sm + WOFF + (wa * 3 + tap) * 3072;
#pragma unroll
                for (int k8 = 0; k8 < 2; k8++) {
                    unsigned a[4][4];
#pragma unroll
                    for (int mt = 0; mt < 4; mt++) {
                        int row = cg * 64 + mt * 16 + lq;
                        uint2 p0 = *(const uint2*)&Wt[row * 24 + k8 * 8 + lr * 2];
                        uint2 p1 = *(const uint2*)&Wt[(row + 8) * 24 + k8 * 8 + lr * 2];
                        a[mt][0] = p0.x; a[mt][2] = p0.y;
                        a[mt][1] = p1.x; a[mt][3] = p1.y;
                    }
#pragma unroll
                    for (int xb = 0; xb < 2; xb++) {
                        if (xb >= nxb) break;
                        const float* Xt = sm + XOFF + h * 6240 + xb * 3120;
#pragma unroll
                        for (int nt = 0; nt < 4; nt++) {
                            int trow = tg * 32 + nt * 8 + lq + tap;
                            uint2 bb = *(const uint2*)&Xt[trow * 24 + k8 * 8 + lr * 2];
#pragma unroll
                            for (int mt = 0; mt < 4; mt++) {
                                asm volatile(
                                    "mma.sync.aligned.m16n8k8.row.col.f32.tf32.tf32.f32 "
                                    "{%0,%1,%2,%3}, {%4,%5,%6,%7}, {%8,%9}, {%0,%1,%2,%3};"
                                    : "+f"(acc[mt][nt][0]), "+f"(acc[mt][nt][1]),
                                      "+f"(acc[mt][nt][2]), "+f"(acc[mt][nt][3])
                                    : "r"(a[mt][0]), "r"(a[mt][1]), "r"(a[mt][2]), "r"(a[mt][3]),
                                      "r"(bb.x), "r"(bb.y));
                            }
                        }
                    }
                }
            }
        }
    }

    // ---- epilogue ----
    if (!fuse) {
        for (int hb = 0; hb < 2; hb++) {
            __syncthreads();
            if (h == hb) {
#pragma unroll
                for (int mt = 0; mt < 4; mt++)
#pragma unroll
                    for (int nt = 0; nt < 4; nt++) {
                        int row = cg * 64 + mt * 16 + lq;
                        int t0 = tg * 32 + nt * 8 + lr * 2;
                        sm[t0 * 130 + row]           = acc[mt][nt][0];
                        sm[(t0 + 1) * 130 + row]     = acc[mt][nt][1];
                        sm[t0 * 130 + row + 8]       = acc[mt][nt][2];
                        sm[(t0 + 1) * 130 + row + 8] = acc[mt][nt][3];
                    }
            }
            __syncthreads();
            int b = b0 + hb;
            for (int e = tid; e < 16384; e += 512) {
                int t = e >> 7, co = e & 127;
                float v = fmaxf(sm[t * 130 + co] + bias[co0 + co], 0.0f);
                float hi, lo;
                split2(v, hi, lo);
                long long o = ((long long)(b * NT + t)) * NC + co0 + co;
                ys[o]         = hi;
                ys[o + PLANE] = lo;
            }
        }
    } else {
        float lsum = 0.0f;
        int b = b0 + h;
#pragma unroll
        for (int mt = 0; mt < 4; mt++)
#pragma unroll
            for (int nt = 0; nt < 4; nt++) {
                int row = cg * 64 + mt * 16 + lq;
                int t0 = tg * 32 + nt * 8 + lr * 2;
#pragma unroll
                for (int hh = 0; hh < 2; hh++) {
                    int co = co0 + row + hh * 8;
                    float bv = bias[co];
                    float y0 = fmaxf(acc[mt][nt][hh * 2 + 0] + bv, 0.0f);
                    float y1 = fmaxf(acc[mt][nt][hh * 2 + 1] + bv, 0.0f);
                    long long i = ((long long)(b * NC + co)) * NT + t0;
                    float2 zh  = *(float2*)&g_zhat[i];
                    float2 zz  = *(const float2*)&z[i];
                    float2 zqv = *(float2*)&g_zq[i];
                    zh.x += y0; zh.y += y1;
                    *(float2*)&g_zhat[i] = zh;
                    zqv.x -= y0; zqv.y -= y1;
                    *(float2*)&g_zq[i] = zqv;
                    float d0 = zh.x - zz.x, d1 = zh.y - zz.y;
                    lsum += d0 * d0 + d1 * d1;
                }
            }
        __syncthreads();
        for (int o = 16; o > 0; o >>= 1) lsum += __shfl_down_sync(0xffffffffu, lsum, o);
        if ((tid & 31) == 0) sm[tid >> 5] = lsum;
        __syncthreads();
        if (tid == 0) {
            float s = 0.0f;
#pragma unroll
            for (int i2 = 0; i2 < 16; i2++) s += sm[i2];
            g_partial[blockIdx.y * 4 + blockIdx.x] = s;
        }
    }
}

// ---------------- per-scale finalize ----------------
__global__ void finalize_kernel(int s) {
    __shared__ float sh[32];
    int tid = threadIdx.x;
    float lsum = (tid < 128) ? g_partial[tid] : 0.0f;
    for (int o = 16; o > 0; o >>= 1) lsum += __shfl_down_sync(0xffffffffu, lsum, o);
    if ((tid & 31) == 0) sh[tid >> 5] = lsum;
    __syncthreads();
    float loss_total = 0.0f;
    if (tid == 0) for (int w = 0; w < 32; w++) loss_total += sh[w];
    __syncthreads();
    int c = g_counts[tid];
    float used = (c > 0) ? 1.0f : 0.0f;
    float p = (float)c / (float)(NB * s);
    float ent = p * logf(p + 1e-10f);
    float us = used;
    for (int o = 16; o > 0; o >>= 1) us += __shfl_down_sync(0xffffffffu, us, o);
    if ((tid & 31) == 0) sh[tid >> 5] = us;
    __syncthreads();
    float used_total = 0.0f;
    if (tid == 0) for (int w = 0; w < 32; w++) used_total += sh[w];
    __syncthreads();
    float es = ent;
    for (int o = 16; o > 0; o >>= 1) es += __shfl_down_sync(0xffffffffu, es, o);
    if ((tid & 31) == 0) sh[tid >> 5] = es;
    __syncthreads();
    float ent_total = 0.0f;
    if (tid == 0) for (int w = 0; w < 32; w++) ent_total += sh[w];
    if (tid == 0) {
        g_sums[0] += used_total * (100.0f / (float)NV);
        g_sums[1] += 1.25f * loss_total / (float)NELEM;
        g_sums[2] += expf(-ent_total);
    }
    g_counts[tid] = 0;
    for (int i = tid; i < NB * NT; i += 1024) g_bestkey[i] = ~0ULL;
}

// ---------------- write outputs ----------------
__global__ void writeout_kernel(float* __restrict__ out, int out_size) {
    long long stride = (long long)gridDim.x * blockDim.x;
    long long t0 = (long long)blockIdx.x * blockDim.x + threadIdx.x;
    for (long long i = t0; i < NELEM && i < out_size; i += stride) out[i] = g_zhat[i];
    if (t0 == 0) {
        if (NELEM + 0 < out_size) out[NELEM + 0] = g_sums[0] / 8.0f;
        if (NELEM + 1 < out_size) out[NELEM + 1] = g_sums[1] / 8.0f;
        if (NELEM + 2 < out_size) out[NELEM + 2] = g_sums[2] / 8.0f;
    }
    if (t0 < NB * NIDX && NELEM + 3 + t0 < out_size)
        out[NELEM + 3 + t0] = (float)g_idxbuf[t0];
}

// ---------------- host ----------------
extern "C" void kernel_launch(void* const* d_in, const int* in_sizes, int n_in,
                              void* d_out, int out_size) {
    const float* z  = (const float*)d_in[0];
    const float* cb = (const float*)d_in[1];
    const float* pw = (const float*)d_in[2];
    const float* pb = (const float*)d_in[3];
    float* out = (float*)d_out;

    void *p_xa = 0, *p_xb = 0, *p_w = 0;
    cudaGetSymbolAddress(&p_xa, g_xs_a);
    cudaGetSymbolAddress(&p_xb, g_xs_b);
    cudaGetSymbolAddress(&p_w,  g_wsp);
    cudaFuncSetAttribute(conv_tc_kernel, cudaFuncAttributeMaxDynamicSharedMemorySize, CONV_SMEM);

    mega_init_kernel<<<26624, 256>>>(z, cb, pw);                   // user launch 0

    for (int q = 0; q < NQ; q++) {
        int s = 1 << q, slog = q, M = NB * s;
        const float* cbq = cb + (long long)q * NV * NC;

        if (s == 1) {
            quant_s1_kernel<<<64, 256>>>(cbq);                     // launch 1 (fused idx+hist)
        } else if (s <= 4) {
            downsample_warp_kernel<<<(NB * NC * s) / 8, 256>>>(s, slog);
            if (s == 2) quantize_small_kernel<2><<<dim3(64, 8), 256>>>(cbq, q);
            else        quantize_small_kernel<4><<<dim3(64, 8), 256>>>(cbq, q);
            post_quantize_kernel<<<(M + 255) / 256, 256>>>(s, slog);
        } else {
            downsample_kernel<<<(NB * NC * s + 255) / 256, 256>>>(s, slog);
            if (s == 8) quantize_small_kernel<8><<<dim3(64, 8), 256>>>(cbq, q);
            else        quantize_gemm_kernel<<<dim3(M / 64, 8), 256>>>(cbq, q, s, slog);
            post_quantize_kernel<<<(M + 255) / 256, 256>>>(s, slog);
        }

        upsample_split_kernel<<<dim3(NB, NT), 128>>>(cbq, s);      // q=0: launch 2

        const float* w0 = (const float*)p_w + ((long long)q * 2 + 0) * 6 * NC * NC;
        const float* w1 = (const float*)p_w + ((long long)q * 2 + 1) * 6 * NC * NC;
        const float* b0 = pb + ((long long)q * 2 + 0) * NC;
        const float* b1 = pb + ((long long)q * 2 + 1) * NC;
        conv_tc_kernel<<<dim3(4, 32), 512, CONV_SMEM>>>(
            (const float*)p_xa, w0, b0, (float*)p_xb, z, 0);       // q=0: launch 3 <-- ncu -s 5
        conv_tc_kernel<<<dim3(4, 32), 512, CONV_SMEM>>>(
            (const float*)p_xb, w1, b1, (float*)0, z, 1);

        finalize_kernel<<<1, 1024>>>(s);
    }

    writeout_kernel<<<2048, 256>>>(out, out_size);
}

// round 9
// speedup vs baseline: 1.1589x; 1.1589x over previous
#include <cuda_runtime.h>
#include <math.h>

#define NB   64
#define NC   512
#define NT   128
#define NV   1024
#define NQ   8
#define NIDX 255
#define NELEM (NB*NC*NT)
#define PLANE ((long long)NB*NT*NC)

// ---------------- device scratch ----------------
__device__ float g_zq[NELEM];
__device__ float g_zhat[NELEM];
__device__ float g_xd[NB*NC*NT];
__device__ float g_xs_a[2ll*NB*NT*NC];   // conv1 input tf32 splits [2][b][t][ci]  (ci pre-permuted)
__device__ float g_xs_b[2ll*NB*NT*NC];   // conv2 input tf32 splits (ci pre-permuted)
__device__ float g_wsp[16ll*6*NC*NC];    // [qd][split*3+tap][co][ci-permuted]
__device__ float g_cnorm[NQ*NV];
__device__ unsigned long long g_bestkey[NB*NT];
__device__ int   g_idxbuf[NB*NIDX];
__device__ int   g_counts[NV];
__device__ float g_partial[256];
__device__ float g_sums[3];

// ---------------- helpers ----------------
__device__ __forceinline__ float tf32r(float x) {
    unsigned u;
    asm("cvt.rna.tf32.f32 %0, %1;" : "=r"(u) : "f"(x));
    return __uint_as_float(u);
}
__device__ __forceinline__ void split2(float x, float& hi, float& lo) {
    hi = tf32r(x);
    lo = tf32r(x - hi);
}
__device__ __forceinline__ int pos8(int c) {           // fragment-ready permutation
    return (c & ~7) | ((c & 3) << 1) | ((c >> 2) & 1);
}
__device__ __forceinline__ unsigned smem_u32(const void* p) {
    unsigned a;
    asm("{ .reg .u64 t; cvta.to.shared.u64 t, %1; cvt.u32.u64 %0, t; }" : "=r"(a) : "l"(p));
    return a;
}
__device__ __forceinline__ unsigned long long dup2(float x) {
    unsigned long long r;
    asm("mov.b64 %0, {%1, %1};" : "=l"(r) : "f"(x));
    return r;
}
__device__ __forceinline__ void fma2(unsigned long long& a, unsigned long long x, unsigned long long y) {
    asm("fma.rn.f32x2 %0, %1, %2, %0;" : "+l"(a) : "l"(x), "l"(y));
}
__device__ __forceinline__ float2 unpack2(unsigned long long v) {
    float2 f;
    asm("mov.b64 {%0, %1}, %2;" : "=f"(f.x), "=f"(f.y) : "l"(v));
    return f;
}

// ---------------- launch 0: init + cnorm + wsplit (fused) ----------------
__global__ void mega_init_kernel(const float* __restrict__ z, const float* __restrict__ cb,
                                 const float* __restrict__ pw) {
    int bx = blockIdx.x;
    int tid = threadIdx.x;
    if (bx < 2048) {
        long long stride = 2048ll * 256;
        long long t0 = (long long)bx * 256 + tid;
        for (long long i = t0; i < NELEM; i += stride) { g_zq[i] = z[i]; g_zhat[i] = 0.0f; }
        if (t0 < 3)   g_sums[t0] = 0.0f;
        if (t0 < NV)  g_counts[t0] = 0;
        if (t0 < 256) g_partial[t0] = 0.0f;
        if (t0 < NB*NT) g_bestkey[t0] = ~0ULL;
    } else if (bx < 2048 + 8192) {
        int row = bx - 2048;
        const float* p = cb + (long long)row * NC;
        float s = 0.0f;
        for (int c = tid; c < NC; c += 256) { float x = p[c]; s += x * x; }
        __shared__ float sh[8];
        for (int o = 16; o > 0; o >>= 1) s += __shfl_down_sync(0xffffffffu, s, o);
        if ((tid & 31) == 0) sh[tid >> 5] = s;
        __syncthreads();
        if (tid == 0) {
            float t = 0.0f;
            for (int w = 0; w < 8; w++) t += sh[w];
            g_cnorm[row] = t;
        }
    } else {
        long long i = (long long)(bx - 10240) * 256 + tid;
        if (i >= 16ll * NC * NC) return;
        int qd = (int)(i >> 18);
        int r  = (int)(i & (NC*NC - 1));
        int co = r >> 9, ci = r & 511;
        const float* src = pw + (((long long)qd * NC + co) * NC + ci) * 3;
        float* dst = g_wsp + (long long)qd * 6 * NC * NC;
        int cip = pos8(ci);
#pragma unroll
        for (int k = 0; k < 3; k++) {
            float hi, lo;
            split2(src[k], hi, lo);
            dst[(long long)k * NC * NC + co * NC + cip]       = hi;
            dst[(long long)(3 + k) * NC * NC + co * NC + cip] = lo;
        }
    }
}

// ---------------- launch 1: fully fused s=1 quantize ----------------
__global__ __launch_bounds__(256) void quant_s1_kernel(const float* __restrict__ cb) {
    __shared__ float xs[512];
    __shared__ unsigned long long wbest[8];
    int b = blockIdx.x;
    int tid = threadIdx.x;
    int wp = tid >> 5, lane = tid & 31;

    for (int i = 0; i < 64; i++) {
        int row = wp * 64 + i;
        float4 v = ((const float4*)(g_zq + (long long)(b * NC + row) * NT))[lane];
        float s = v.x + v.y + v.z + v.w;
        for (int o = 16; o > 0; o >>= 1) s += __shfl_xor_sync(0xffffffffu, s, o);
        if (lane == 0) xs[row] = s * (1.0f / 128.0f);
    }
    __syncthreads();

    float bestv = INFINITY;
    int besti = 0;
    for (int cc = 0; cc < 128; cc++) {
        int code = wp * 128 + cc;
        const float* cbr = cb + (long long)code * 512;
        float d = 0.0f;
#pragma unroll
        for (int e = 0; e < 16; e++) d += xs[lane + 32 * e] * cbr[lane + 32 * e];
        for (int o = 16; o > 0; o >>= 1) d += __shfl_xor_sync(0xffffffffu, d, o);
        float sc = g_cnorm[code] - 2.0f * d;
        if (sc < bestv) { bestv = sc; besti = code; }
    }
    if (lane == 0) {
        unsigned u = __float_as_uint(bestv);
        u = (u & 0x80000000u) ? ~u : (u | 0x80000000u);
        wbest[wp] = ((unsigned long long)u << 32) | (unsigned)besti;
    }
    __syncthreads();
    if (tid == 0) {
        unsigned long long k = wbest[0];
        for (int i = 1; i < 8; i++) if (wbest[i] < k) k = wbest[i];
        int idx = (int)(k & 0xFFFFFFFFULL);
        g_idxbuf[b * NIDX] = idx;
        atomicAdd(&g_counts[idx], 1);
    }
}

// ---------------- downsample ----------------
__global__ void downsample_warp_kernel(int s, int slog) {
    int r = NT >> slog;
    int i = blockIdx.x * 8 + (threadIdx.x >> 5);
    int lane = threadIdx.x & 31;
    if (i >= NB * NC * s) return;
    int j  = i & (s - 1);
    int bc = i >> slog;
    const float* src = g_zq + (long long)bc * NT + j * r;
    float acc;
    if (r == 64) { float2 v = ((const float2*)src)[lane]; acc = v.x + v.y; }
    else         { acc = src[lane]; }
    for (int o = 16; o > 0; o >>= 1) acc += __shfl_xor_sync(0xffffffffu, acc, o);
    if (lane == 0) g_xd[i] = acc * (1.0f / (float)r);
}
__global__ void downsample_kernel(int s, int slog) {
    int total = NB * NC * s;
    int r = NT >> slog;
    int i = blockIdx.x * blockDim.x + threadIdx.x;
    if (i >= total) return;
    int j  = i & (s - 1);
    int bc = i >> slog;
    const float* src = g_zq + (long long)bc * NT + j * r;
    float acc = 0.0f;
    for (int k = 0; k < r; k++) acc += src[k];
    g_xd[i] = acc * (1.0f / (float)r);
}

// ---------------- quantize (s in 2..8) ----------------
template<int S>
__global__ __launch_bounds__(256) void quantize_small_kernel(const float* __restrict__ cb, int q) {
    __shared__ float xs[S][512];
    int b  = blockIdx.x;
    int c0 = blockIdx.y * 128;
    int tid = threadIdx.x;
    for (int e = tid; e < S * 512; e += 256) {
        int j = e >> 9, ch = e & 511;
        xs[j][ch] = g_xd[(b * 512 + ch) * S + j];
    }
    __syncthreads();
    int w = tid >> 5, lane = tid & 31;
    float bestv[S]; int besti[S];
#pragma unroll
    for (int j = 0; j < S; j++) { bestv[j] = INFINITY; besti[j] = 0; }
    for (int cc = 0; cc < 16; cc++) {
        int code = c0 + w * 16 + cc;
        const float* cbr = cb + (long long)code * 512;
        float cv[16];
#pragma unroll
        for (int e = 0; e < 16; e++) cv[e] = cbr[lane + 32 * e];
        float cn = g_cnorm[q * NV + code];
#pragma unroll
        for (int j = 0; j < S; j++) {
            float d = 0.0f;
#pragma unroll
            for (int e = 0; e < 16; e++) d += xs[j][lane + 32 * e] * cv[e];
            for (int o = 16; o > 0; o >>= 1) d += __shfl_xor_sync(0xffffffffu, d, o);
            float sc = cn - 2.0f * d;
            if (sc < bestv[j]) { bestv[j] = sc; besti[j] = code; }
        }
    }
    if (lane == 0) {
#pragma unroll
        for (int j = 0; j < S; j++) {
            unsigned u = __float_as_uint(bestv[j]);
            u = (u & 0x80000000u) ? ~u : (u | 0x80000000u);
            atomicMin(&g_bestkey[b * S + j], ((unsigned long long)u << 32) | (unsigned)besti[j]);
        }
    }
}

// ---------------- quantize (s>=16) ----------------
__global__ __launch_bounds__(256) void quantize_gemm_kernel(
    const float* __restrict__ cb, int q, int s, int slog)
{
    const int m0 = blockIdx.x * 64;
    const int n0 = blockIdx.y * 128;
    __shared__ float As[32][65];
    __shared__ float Bs[32][130];
    const int tid = threadIdx.x;
    const int ti = tid >> 4, tj = tid & 15;
    unsigned long long acc[4][4];
#pragma unroll
    for (int r = 0; r < 4; r++)
#pragma unroll
        for (int c = 0; c < 4; c++) acc[r][c] = 0ULL;
    for (int kc = 0; kc < NC; kc += 32) {
#pragma unroll
        for (int it = 0; it < 8; it++) {
            int e = tid + 256 * it;
            int m = e & 63, kk = e >> 6;
            int gm = m0 + m;
            int b = gm >> slog, j = gm & (s - 1);
            As[kk][m] = g_xd[(((long long)b * NC + (kc + kk)) << slog) + j];
        }
#pragma unroll
        for (int it = 0; it < 16; it++) {
            int e = tid + 256 * it;
            int kk = e & 31, n = e >> 5;
            Bs[kk][n] = cb[(long long)(n0 + n) * NC + kc + kk];
        }
        __syncthreads();
#pragma unroll 8
        for (int kk = 0; kk < 32; kk++) {
            unsigned long long a2[4], b2[4];
#pragma unroll
            for (int r = 0; r < 4; r++) a2[r] = dup2(As[kk][ti + 16 * r]);
#pragma unroll
            for (int c = 0; c < 4; c++) b2[c] = *(const unsigned long long*)&Bs[kk][2 * tj + 32 * c];
#pragma unroll
            for (int r = 0; r < 4; r++)
#pragma unroll
                for (int c = 0; c < 4; c++) fma2(acc[r][c], a2[r], b2[c]);
        }
        __syncthreads();
    }
    float bestv[4]; int besti[4];
#pragma unroll
    for (int r = 0; r < 4; r++) { bestv[r] = INFINITY; besti[r] = 0; }
#pragma unroll
    for (int c = 0; c < 4; c++) {
        int n = n0 + 2 * tj + 32 * c;
        float cn0 = g_cnorm[q * NV + n], cn1 = g_cnorm[q * NV + n + 1];
#pragma unroll
        for (int r = 0; r < 4; r++) {
            float2 dv = unpack2(acc[r][c]);
            float s0 = cn0 - 2.0f * dv.x, s1 = cn1 - 2.0f * dv.y;
            if (s0 < bestv[r]) { bestv[r] = s0; besti[r] = n; }
            if (s1 < bestv[r]) { bestv[r] = s1; besti[r] = n + 1; }
        }
    }
#pragma unroll
    for (int r = 0; r < 4; r++) {
        float v = bestv[r]; int ix = besti[r];
        for (int off = 8; off > 0; off >>= 1) {
            float ov = __shfl_down_sync(0xffffffffu, v, off, 16);
            int   oi = __shfl_down_sync(0xffffffffu, ix, off, 16);
            if (ov < v || (ov == v && oi < ix)) { v = ov; ix = oi; }
        }
        if (tj == 0) {
            unsigned u = __float_as_uint(v);
            u = (u & 0x80000000u) ? ~u : (u | 0x80000000u);
            atomicMin(&g_bestkey[m0 + ti + 16 * r], ((unsigned long long)u << 32) | (unsigned)ix);
        }
    }
}

// ---------------- extract idx + histogram (s>=2) ----------------
__global__ void post_quantize_kernel(int s, int slog) {
    int m = blockIdx.x * blockDim.x + threadIdx.x;
    if (m >= NB * s) return;
    int v = (int)(g_bestkey[m] & 0xFFFFFFFFULL);
    int b = m >> slog, j = m & (s - 1);
    g_idxbuf[b * NIDX + (s - 1) + j] = v;
    atomicAdd(&g_counts[v], 1);
}

// ---------------- upsample -> tf32 splits (ci permuted) ----------------
__global__ void upsample_split_kernel(const float* __restrict__ cb, int s) {
    int b = blockIdx.x, t = blockIdx.y;
    float u = (t + 0.5f) * ((float)s / 128.0f) - 0.5f;
    float jf = floorf(u);
    float f = u - jf;
    int j0 = (int)jf, j1 = j0 + 1;
    if (j0 < 0) j0 = 0; if (j0 > s - 1) j0 = s - 1;
    if (j1 < 0) j1 = 0; if (j1 > s - 1) j1 = s - 1;
    int v0 = g_idxbuf[b * NIDX + (s - 1) + j0];
    int v1 = g_idxbuf[b * NIDX + (s - 1) + j1];
    const float* c0 = cb + (long long)v0 * NC;
    const float* c1 = cb + (long long)v1 * NC;
    float w1 = f, w0 = 1.0f - f;
    long long base = ((long long)(b * NT + t)) * NC;
    for (int c = threadIdx.x; c < NC; c += 128) {
        float val = w0 * c0[c] + w1 * c1[c];
        float hi, lo;
        split2(val, hi, lo);
        int cp = pos8(c);
        g_xs_a[base + cp]         = hi;
        g_xs_a[base + cp + PLANE] = lo;
    }
}

// ---------------- tf32 mma conv: cp.async double-buffered X, reg-prefetched W ----------------
// smem floats: W 6*3072=18432 @0; X 2 bufs * (2 batches * 2 splits * 130*24 = 12480) @18432.
#define WOFF 0
#define XOFF 18432
#define XBUF 12480
#define CONV_SMEM ((18432 + 2*12480)*4)   // 173568 B
__global__ __launch_bounds__(512, 1) void conv_tc_kernel(
    const float* __restrict__ xs,   // [2][b][t][ci-permuted]
    const float* __restrict__ wsp,  // [6][co][ci-permuted] for this layer
    const float* __restrict__ bias,
    float* __restrict__ ys,
    const float* __restrict__ z, int fuse)
{
    extern __shared__ float sm[];
    const unsigned sbase = smem_u32(sm);
    const int tid = threadIdx.x, lane = tid & 31, wid = tid >> 5;
    const int h = wid >> 3, wh = wid & 7;
    const int cg = wh >> 2, tg = wh & 3;
    const int b0 = blockIdx.y * 2, co0 = blockIdx.x * 128;
    const int lq = lane >> 2, lr = lane & 3;

    // zero halo rows (rows 0 and 129 of each (buf,hb,sp)) once
    for (int e = tid; e < 16 * 24; e += 512) {
        int r = e / 24, w = e - r * 24;
        int buf = (r >> 3) & 1, hb = (r >> 2) & 1, sp = (r >> 1) & 1, rr = r & 1;
        sm[XOFF + buf * XBUF + hb * 6240 + sp * 3120 + (rr ? 129 : 0) * 24 + w] = 0.0f;
    }

    float acc[4][4][4];
#pragma unroll
    for (int mt = 0; mt < 4; mt++)
#pragma unroll
        for (int nt = 0; nt < 4; nt++)
#pragma unroll
            for (int r = 0; r < 4; r++) acc[mt][nt][r] = 0.0f;

    // W prefetch (chunk 0)
    float4 wpre[6];
#pragma unroll
    for (int i = 0; i < 6; i++) {
        int e = tid + 512 * i;
        int tile = e >> 9, r = e & 511, row = r >> 2, q = r & 3;
        wpre[i] = *(const float4*)(wsp + (long long)tile * (NC * NC)
                                   + (long long)(co0 + row) * NC + q * 4);
    }
    // X chunk 0 -> buf 0
#pragma unroll
    for (int i = 0; i < 4; i++) {
        int e = tid + 512 * i;
        int hb = e >> 10, rem = e & 1023, sp = rem >> 9, r = rem & 511;
        int row = r >> 2, q = r & 3;
        const float* src = xs + (long long)sp * PLANE
                           + ((long long)((b0 + hb) * NT + row)) * NC + q * 4;
        unsigned dst = sbase + (unsigned)(XOFF + hb * 6240 + sp * 3120 + (row + 1) * 24 + q * 4) * 4u;
        asm volatile("cp.async.cg.shared.global [%0], [%1], 16;" :: "r"(dst), "l"(src));
    }
    asm volatile("cp.async.commit_group;");

    for (int ch = 0; ch < 32; ch++) {
        const int buf = ch & 1;
        asm volatile("cp.async.wait_group 0;");
        __syncthreads();   // X(ch) visible everywhere; MMA(ch-1) complete (W + buf reuse safe)

        // store W(ch): straight float4 (gmem pre-permuted)
#pragma unroll
        for (int i = 0; i < 6; i++) {
            int e = tid + 512 * i;
            int tile = e >> 9, r = e & 511, row = r >> 2, q = r & 3;
            *(float4*)(sm + WOFF + tile * 3072 + row * 24 + q * 4) = wpre[i];
        }
        if (ch < 31) {
            int ci1 = (ch + 1) * 16;
            // issue X(ch+1) -> other buffer
#pragma unroll
            for (int i = 0; i < 4; i++) {
                int e = tid + 512 * i;
                int hb = e >> 10, rem = e & 1023, sp = rem >> 9, r = rem & 511;
                int row = r >> 2, q = r & 3;
                const float* src = xs + (long long)sp * PLANE
                                   + ((long long)((b0 + hb) * NT + row)) * NC + ci1 + q * 4;
                unsigned dst = sbase + (unsigned)(XOFF + (buf ^ 1) * XBUF + hb * 6240
                                                  + sp * 3120 + (row + 1) * 24 + q * 4) * 4u;
                asm volatile("cp.async.cg.shared.global [%0], [%1], 16;" :: "r"(dst), "l"(src));
            }
            asm volatile("cp.async.commit_group;");
            // W prefetch (ch+1)
#pragma unroll
            for (int i = 0; i < 6; i++) {
                int e = tid + 512 * i;
                int tile = e >> 9, r = e & 511, row = r >> 2, q = r & 3;
                wpre[i] = *(const float4*)(wsp + (long long)tile * (NC * NC)
                                           + (long long)(co0 + row) * NC + ci1 + q * 4);
            }
        }
        __syncthreads();   // W(ch) visible

        // ---- mma: 3 terms (whi,xhi), (whi,xlo), (wlo,xhi) ----
#pragma unroll
        for (int wa = 0; wa < 2; wa++) {
            const int nxb = (wa == 0) ? 2 : 1;
            for (int tap = 0; tap < 3; tap++) {
                const float* Wt = sm + WOFF + (wa * 3 + tap) * 3072;
#pragma unroll
                for (int k8 = 0; k8 < 2; k8++) {
                    unsigned a[4][4];
#pragma unroll
                    for (int mt = 0; mt < 4; mt++) {
                        int row = cg * 64 + mt * 16 + lq;
                        uint2 p0 = *(const uint2*)&Wt[row * 24 + k8 * 8 + lr * 2];
                        uint2 p1 = *(const uint2*)&Wt[(row + 8) * 24 + k8 * 8 + lr * 2];
                        a[mt][0] = p0.x; a[mt][2] = p0.y;
                        a[mt][1] = p1.x; a[mt][3] = p1.y;
                    }
#pragma unroll
                    for (int xb = 0; xb < 2; xb++) {
                        if (xb >= nxb) break;
                        const float* Xt = sm + XOFF + buf * XBUF + h * 6240 + xb * 3120;
#pragma unroll
                        for (int nt = 0; nt < 4; nt++) {
                            int trow = tg * 32 + nt * 8 + lq + tap;
                            uint2 bb = *(const uint2*)&Xt[trow * 24 + k8 * 8 + lr * 2];
#pragma unroll
                            for (int mt = 0; mt < 4; mt++) {
                                asm volatile(
                                    "mma.sync.aligned.m16n8k8.row.col.f32.tf32.tf32.f32 "
                                    "{%0,%1,%2,%3}, {%4,%5,%6,%7}, {%8,%9}, {%0,%1,%2,%3};"
                                    : "+f"(acc[mt][nt][0]), "+f"(acc[mt][nt][1]),
                                      "+f"(acc[mt][nt][2]), "+f"(acc[mt][nt][3])
                                    : "r"(a[mt][0]), "r"(a[mt][1]), "r"(a[mt][2]), "r"(a[mt][3]),
                                      "r"(bb.x), "r"(bb.y));
                            }
                        }
                    }
                }
            }
        }
    }

    // ---- epilogue ----
    if (!fuse) {
        for (int hb = 0; hb < 2; hb++) {
            __syncthreads();
            if (h == hb) {
#pragma unroll
                for (int mt = 0; mt < 4; mt++)
#pragma unroll
                    for (int nt = 0; nt < 4; nt++) {
                        int row = cg * 64 + mt * 16 + lq;
                        int t0 = tg * 32 + nt * 8 + lr * 2;
                        sm[t0 * 130 + row]           = acc[mt][nt][0];
                        sm[(t0 + 1) * 130 + row]     = acc[mt][nt][1];
                        sm[t0 * 130 + row + 8]       = acc[mt][nt][2];
                        sm[(t0 + 1) * 130 + row + 8] = acc[mt][nt][3];
                    }
            }
            __syncthreads();
            int b = b0 + hb;
            for (int e = tid; e < 16384; e += 512) {
                int t = e >> 7, co = e & 127;
                float v = fmaxf(sm[t * 130 + co] + bias[co0 + co], 0.0f);
                float hi, lo;
                split2(v, hi, lo);
                long long o = ((long long)(b * NT + t)) * NC + co0 + pos8(co);
                ys[o]         = hi;
                ys[o + PLANE] = lo;
            }
        }
    } else {
        float lsum = 0.0f;
        int b = b0 + h;
#pragma unroll
        for (int mt = 0; mt < 4; mt++)
#pragma unroll
            for (int nt = 0; nt < 4; nt++) {
                int row = cg * 64 + mt * 16 + lq;
                int t0 = tg * 32 + nt * 8 + lr * 2;
#pragma unroll
                for (int hh = 0; hh < 2; hh++) {
                    int co = co0 + row + hh * 8;
                    float bv = bias[co];
                    float y0 = fmaxf(acc[mt][nt][hh * 2 + 0] + bv, 0.0f);
                    float y1 = fmaxf(acc[mt][nt][hh * 2 + 1] + bv, 0.0f);
                    long long i = ((long long)(b * NC + co)) * NT + t0;
                    float2 zh  = *(float2*)&g_zhat[i];
                    float2 zz  = *(const float2*)&z[i];
                    float2 zqv = *(float2*)&g_zq[i];
                    zh.x += y0; zh.y += y1;
                    *(float2*)&g_zhat[i] = zh;
                    zqv.x -= y0; zqv.y -= y1;
                    *(float2*)&g_zq[i] = zqv;
                    float d0 = zh.x - zz.x, d1 = zh.y - zz.y;
                    lsum += d0 * d0 + d1 * d1;
                }
            }
        __syncthreads();
        for (int o = 16; o > 0; o >>= 1) lsum += __shfl_down_sync(0xffffffffu, lsum, o);
        if ((tid & 31) == 0) sm[tid >> 5] = lsum;
        __syncthreads();
        if (tid == 0) {
            float s = 0.0f;
#pragma unroll
            for (int i2 = 0; i2 < 16; i2++) s += sm[i2];
            g_partial[blockIdx.y * 4 + blockIdx.x] = s;
        }
    }
}

// ---------------- per-scale finalize ----------------
__global__ void finalize_kernel(int s) {
    __shared__ float sh[32];
    int tid = threadIdx.x;
    float lsum = (tid < 128) ? g_partial[tid] : 0.0f;
    for (int o = 16; o > 0; o >>= 1) lsum += __shfl_down_sync(0xffffffffu, lsum, o);
    if ((tid & 31) == 0) sh[tid >> 5] = lsum;
    __syncthreads();
    float loss_total = 0.0f;
    if (tid == 0) for (int w = 0; w < 32; w++) loss_total += sh[w];
    __syncthreads();
    int c = g_counts[tid];
    float used = (c > 0) ? 1.0f : 0.0f;
    float p = (float)c / (float)(NB * s);
    float ent = p * logf(p + 1e-10f);
    float us = used;
    for (int o = 16; o > 0; o >>= 1) us += __shfl_down_sync(0xffffffffu, us, o);
    if ((tid & 31) == 0) sh[tid >> 5] = us;
    __syncthreads();
    float used_total = 0.0f;
    if (tid == 0) for (int w = 0; w < 32; w++) used_total += sh[w];
    __syncthreads();
    float es = ent;
    for (int o = 16; o > 0; o >>= 1) es += __shfl_down_sync(0xffffffffu, es, o);
    if ((tid & 31) == 0) sh[tid >> 5] = es;
    __syncthreads();
    float ent_total = 0.0f;
    if (tid == 0) for (int w = 0; w < 32; w++) ent_total += sh[w];
    if (tid == 0) {
        g_sums[0] += used_total * (100.0f / (float)NV);
        g_sums[1] += 1.25f * loss_total / (float)NELEM;
        g_sums[2] += expf(-ent_total);
    }
    g_counts[tid] = 0;
    for (int i = tid; i < NB * NT; i += 1024) g_bestkey[i] = ~0ULL;
}

// ---------------- write outputs ----------------
__global__ void writeout_kernel(float* __restrict__ out, int out_size) {
    long long stride = (long long)gridDim.x * blockDim.x;
    long long t0 = (long long)blockIdx.x * blockDim.x + threadIdx.x;
    for (long long i = t0; i < NELEM && i < out_size; i += stride) out[i] = g_zhat[i];
    if (t0 == 0) {
        if (NELEM + 0 < out_size) out[NELEM + 0] = g_sums[0] / 8.0f;
        if (NELEM + 1 < out_size) out[NELEM + 1] = g_sums[1] / 8.0f;
        if (NELEM + 2 < out_size) out[NELEM + 2] = g_sums[2] / 8.0f;
    }
    if (t0 < NB * NIDX && NELEM + 3 + t0 < out_size)
        out[NELEM + 3 + t0] = (float)g_idxbuf[t0];
}

// ---------------- host ----------------
extern "C" void kernel_launch(void* const* d_in, const int* in_sizes, int n_in,
                              void* d_out, int out_size) {
    const float* z  = (const float*)d_in[0];
    const float* cb = (const float*)d_in[1];
    const float* pw = (const float*)d_in[2];
    const float* pb = (const float*)d_in[3];
    float* out = (float*)d_out;

    void *p_xa = 0, *p_xb = 0, *p_w = 0;
    cudaGetSymbolAddress(&p_xa, g_xs_a);
    cudaGetSymbolAddress(&p_xb, g_xs_b);
    cudaGetSymbolAddress(&p_w,  g_wsp);
    cudaFuncSetAttribute(conv_tc_kernel, cudaFuncAttributeMaxDynamicSharedMemorySize, CONV_SMEM);

    mega_init_kernel<<<26624, 256>>>(z, cb, pw);                   // user launch 0

    for (int q = 0; q < NQ; q++) {
        int s = 1 << q, slog = q, M = NB * s;
        const float* cbq = cb + (long long)q * NV * NC;

        if (s == 1) {
            quant_s1_kernel<<<64, 256>>>(cbq);                     // launch 1
        } else if (s <= 4) {
            downsample_warp_kernel<<<(NB * NC * s) / 8, 256>>>(s, slog);
            if (s == 2) quantize_small_kernel<2><<<dim3(64, 8), 256>>>(cbq, q);
            else        quantize_small_kernel<4><<<dim3(64, 8), 256>>>(cbq, q);
            post_quantize_kernel<<<(M + 255) / 256, 256>>>(s, slog);
        } else {
            downsample_kernel<<<(NB * NC * s + 255) / 256, 256>>>(s, slog);
            if (s == 8) quantize_small_kernel<8><<<dim3(64, 8), 256>>>(cbq, q);
            else        quantize_gemm_kernel<<<dim3(M / 64, 8), 256>>>(cbq, q, s, slog);
            post_quantize_kernel<<<(M + 255) / 256, 256>>>(s, slog);
        }

        upsample_split_kernel<<<dim3(NB, NT), 128>>>(cbq, s);      // q=0: launch 2

        const float* w0 = (const float*)p_w + ((long long)q * 2 + 0) * 6 * NC * NC;
        const float* w1 = (const float*)p_w + ((long long)q * 2 + 1) * 6 * NC * NC;
        const float* b0 = pb + ((long long)q * 2 + 0) * NC;
        const float* b1 = pb + ((long long)q * 2 + 1) * NC;
        conv_tc_kernel<<<dim3(4, 32), 512, CONV_SMEM>>>(
            (const float*)p_xa, w0, b0, (float*)p_xb, z, 0);       // q=0: launch 3 <-- ncu -s 5
        conv_tc_kernel<<<dim3(4, 32), 512, CONV_SMEM>>>(
            (const float*)p_xb, w1, b1, (float*)0, z, 1);

        finalize_kernel<<<1, 1024>>>(s);
    }

    writeout_kernel<<<2048, 256>>>(out, out_size);
}

// round 10
// speedup vs baseline: 1.2709x; 1.0967x over previous
#include <cuda_runtime.h>
#include <math.h>

#define NB   64
#define NC   512
#define NT   128
#define NV   1024
#define NQ   8
#define NIDX 255
#define NELEM (NB*NC*NT)
#define PLANE ((long long)NB*NT*NC)

// ---------------- device scratch ----------------
__device__ float g_zq[NELEM];
__device__ float g_zhat[NELEM];
__device__ float g_xd[NB*NC*NT];
__device__ float g_xs_a[2ll*NB*NT*NC];   // conv1 input tf32 splits [2][b][t][ci-permuted]
__device__ float g_xs_b[2ll*NB*NT*NC];   // conv2 input tf32 splits
__device__ float g_wsp[16ll*6*NC*NC];    // [qd][split*3+tap][co][ci-permuted]
__device__ float g_cnorm[NQ*NV];
__device__ unsigned long long g_bestkey[NB*NT];
__device__ int   g_idxbuf[NB*NIDX];
__device__ int   g_counts[NV];
__device__ float g_partial[256];
__device__ float g_sums[3];

// ---------------- helpers ----------------
__device__ __forceinline__ float tf32r(float x) {
    unsigned u;
    asm("cvt.rna.tf32.f32 %0, %1;" : "=r"(u) : "f"(x));
    return __uint_as_float(u);
}
__device__ __forceinline__ void split2(float x, float& hi, float& lo) {
    hi = tf32r(x);
    lo = tf32r(x - hi);
}
__device__ __forceinline__ int pos8(int c) {           // fragment-ready permutation
    return (c & ~7) | ((c & 3) << 1) | ((c >> 2) & 1);
}
__device__ __forceinline__ unsigned smem_u32(const void* p) {
    unsigned a;
    asm("{ .reg .u64 t; cvta.to.shared.u64 t, %1; cvt.u32.u64 %0, t; }" : "=r"(a) : "l"(p));
    return a;
}
__device__ __forceinline__ unsigned long long dup2(float x) {
    unsigned long long r;
    asm("mov.b64 %0, {%1, %1};" : "=l"(r) : "f"(x));
    return r;
}
__device__ __forceinline__ void fma2(unsigned long long& a, unsigned long long x, unsigned long long y) {
    asm("fma.rn.f32x2 %0, %1, %2, %0;" : "+l"(a) : "l"(x), "l"(y));
}
__device__ __forceinline__ float2 unpack2(unsigned long long v) {
    float2 f;
    asm("mov.b64 {%0, %1}, %2;" : "=f"(f.x), "=f"(f.y) : "l"(v));
    return f;
}
__device__ __forceinline__ void mma_tf32(float* d, const unsigned* a, uint2 b) {
    asm volatile(
        "mma.sync.aligned.m16n8k8.row.col.f32.tf32.tf32.f32 "
        "{%0,%1,%2,%3}, {%4,%5,%6,%7}, {%8,%9}, {%0,%1,%2,%3};"
        : "+f"(d[0]), "+f"(d[1]), "+f"(d[2]), "+f"(d[3])
        : "r"(a[0]), "r"(a[1]), "r"(a[2]), "r"(a[3]), "r"(b.x), "r"(b.y));
}

// ---------------- launch 0: init + cnorm + wsplit (fused) ----------------
__global__ void mega_init_kernel(const float* __restrict__ z, const float* __restrict__ cb,
                                 const float* __restrict__ pw) {
    int bx = blockIdx.x;
    int tid = threadIdx.x;
    if (bx < 2048) {
        long long stride = 2048ll * 256;
        long long t0 = (long long)bx * 256 + tid;
        for (long long i = t0; i < NELEM; i += stride) { g_zq[i] = z[i]; g_zhat[i] = 0.0f; }
        if (t0 < 3)   g_sums[t0] = 0.0f;
        if (t0 < NV)  g_counts[t0] = 0;
        if (t0 < 256) g_partial[t0] = 0.0f;
        if (t0 < NB*NT) g_bestkey[t0] = ~0ULL;
    } else if (bx < 2048 + 8192) {
        int row = bx - 2048;
        const float* p = cb + (long long)row * NC;
        float s = 0.0f;
        for (int c = tid; c < NC; c += 256) { float x = p[c]; s += x * x; }
        __shared__ float sh[8];
        for (int o = 16; o > 0; o >>= 1) s += __shfl_down_sync(0xffffffffu, s, o);
        if ((tid & 31) == 0) sh[tid >> 5] = s;
        __syncthreads();
        if (tid == 0) {
            float t = 0.0f;
            for (int w = 0; w < 8; w++) t += sh[w];
            g_cnorm[row] = t;
        }
    } else {
        long long i = (long long)(bx - 10240) * 256 + tid;
        if (i >= 16ll * NC * NC) return;
        int qd = (int)(i >> 18);
        int r  = (int)(i & (NC*NC - 1));
        int co = r >> 9, ci = r & 511;
        const float* src = pw + (((long long)qd * NC + co) * NC + ci) * 3;
        float* dst = g_wsp + (long long)qd * 6 * NC * NC;
        int cip = pos8(ci);
#pragma unroll
        for (int k = 0; k < 3; k++) {
            float hi, lo;
            split2(src[k], hi, lo);
            dst[(long long)k * NC * NC + co * NC + cip]       = hi;
            dst[(long long)(3 + k) * NC * NC + co * NC + cip] = lo;
        }
    }
}

// ---------------- launch 1: fully fused s=1 quantize ----------------
__global__ __launch_bounds__(256) void quant_s1_kernel(const float* __restrict__ cb) {
    __shared__ float xs[512];
    __shared__ unsigned long long wbest[8];
    int b = blockIdx.x;
    int tid = threadIdx.x;
    int wp = tid >> 5, lane = tid & 31;

    for (int i = 0; i < 64; i++) {
        int row = wp * 64 + i;
        float4 v = ((const float4*)(g_zq + (long long)(b * NC + row) * NT))[lane];
        float s = v.x + v.y + v.z + v.w;
        for (int o = 16; o > 0; o >>= 1) s += __shfl_xor_sync(0xffffffffu, s, o);
        if (lane == 0) xs[row] = s * (1.0f / 128.0f);
    }
    __syncthreads();

    float bestv = INFINITY;
    int besti = 0;
    for (int cc = 0; cc < 128; cc++) {
        int code = wp * 128 + cc;
        const float* cbr = cb + (long long)code * 512;
        float d = 0.0f;
#pragma unroll
        for (int e = 0; e < 16; e++) d += xs[lane + 32 * e] * cbr[lane + 32 * e];
        for (int o = 16; o > 0; o >>= 1) d += __shfl_xor_sync(0xffffffffu, d, o);
        float sc = g_cnorm[code] - 2.0f * d;
        if (sc < bestv) { bestv = sc; besti = code; }
    }
    if (lane == 0) {
        unsigned u = __float_as_uint(bestv);
        u = (u & 0x80000000u) ? ~u : (u | 0x80000000u);
        wbest[wp] = ((unsigned long long)u << 32) | (unsigned)besti;
    }
    __syncthreads();
    if (tid == 0) {
        unsigned long long k = wbest[0];
        for (int i = 1; i < 8; i++) if (wbest[i] < k) k = wbest[i];
        int idx = (int)(k & 0xFFFFFFFFULL);
        g_idxbuf[b * NIDX] = idx;
        atomicAdd(&g_counts[idx], 1);
    }
}

// ---------------- downsample ----------------
__global__ void downsample_warp_kernel(int s, int slog) {
    int r = NT >> slog;
    int i = blockIdx.x * 8 + (threadIdx.x >> 5);
    int lane = threadIdx.x & 31;
    if (i >= NB * NC * s) return;
    int j  = i & (s - 1);
    int bc = i >> slog;
    const float* src = g_zq + (long long)bc * NT + j * r;
    float acc;
    if (r == 64) { float2 v = ((const float2*)src)[lane]; acc = v.x + v.y; }
    else         { acc = src[lane]; }
    for (int o = 16; o > 0; o >>= 1) acc += __shfl_xor_sync(0xffffffffu, acc, o);
    if (lane == 0) g_xd[i] = acc * (1.0f / (float)r);
}
__global__ void downsample_kernel(int s, int slog) {
    int total = NB * NC * s;
    int r = NT >> slog;
    int i = blockIdx.x * blockDim.x + threadIdx.x;
    if (i >= total) return;
    int j  = i & (s - 1);
    int bc = i >> slog;
    const float* src = g_zq + (long long)bc * NT + j * r;
    float acc = 0.0f;
    for (int k = 0; k < r; k++) acc += src[k];
    g_xd[i] = acc * (1.0f / (float)r);
}

// ---------------- quantize (s in 2..8) ----------------
template<int S>
__global__ __launch_bounds__(256) void quantize_small_kernel(const float* __restrict__ cb, int q) {
    __shared__ float xs[S][512];
    int b  = blockIdx.x;
    int c0 = blockIdx.y * 128;
    int tid = threadIdx.x;
    for (int e = tid; e < S * 512; e += 256) {
        int j = e >> 9, ch = e & 511;
        xs[j][ch] = g_xd[(b * 512 + ch) * S + j];
    }
    __syncthreads();
    int w = tid >> 5, lane = tid & 31;
    float bestv[S]; int besti[S];
#pragma unroll
    for (int j = 0; j < S; j++) { bestv[j] = INFINITY; besti[j] = 0; }
    for (int cc = 0; cc < 16; cc++) {
        int code = c0 + w * 16 + cc;
        const float* cbr = cb + (long long)code * 512;
        float cv[16];
#pragma unroll
        for (int e = 0; e < 16; e++) cv[e] = cbr[lane + 32 * e];
        float cn = g_cnorm[q * NV + code];
#pragma unroll
        for (int j = 0; j < S; j++) {
            float d = 0.0f;
#pragma unroll
            for (int e = 0; e < 16; e++) d += xs[j][lane + 32 * e] * cv[e];
            for (int o = 16; o > 0; o >>= 1) d += __shfl_xor_sync(0xffffffffu, d, o);
            float sc = cn - 2.0f * d;
            if (sc < bestv[j]) { bestv[j] = sc; besti[j] = code; }
        }
    }
    if (lane == 0) {
#pragma unroll
        for (int j = 0; j < S; j++) {
            unsigned u = __float_as_uint(bestv[j]);
            u = (u & 0x80000000u) ? ~u : (u | 0x80000000u);
            atomicMin(&g_bestkey[b * S + j], ((unsigned long long)u << 32) | (unsigned)besti[j]);
        }
    }
}

// ---------------- quantize (s>=16) ----------------
__global__ __launch_bounds__(256) void quantize_gemm_kernel(
    const float* __restrict__ cb, int q, int s, int slog)
{
    const int m0 = blockIdx.x * 64;
    const int n0 = blockIdx.y * 128;
    __shared__ float As[32][65];
    __shared__ float Bs[32][130];
    const int tid = threadIdx.x;
    const int ti = tid >> 4, tj = tid & 15;
    unsigned long long acc[4][4];
#pragma unroll
    for (int r = 0; r < 4; r++)
#pragma unroll
        for (int c = 0; c < 4; c++) acc[r][c] = 0ULL;
    for (int kc = 0; kc < NC; kc += 32) {
#pragma unroll
        for (int it = 0; it < 8; it++) {
            int e = tid + 256 * it;
            int m = e & 63, kk = e >> 6;
            int gm = m0 + m;
            int b = gm >> slog, j = gm & (s - 1);
            As[kk][m] = g_xd[(((long long)b * NC + (kc + kk)) << slog) + j];
        }
#pragma unroll
        for (int it = 0; it < 16; it++) {
            int e = tid + 256 * it;
            int kk = e & 31, n = e >> 5;
            Bs[kk][n] = cb[(long long)(n0 + n) * NC + kc + kk];
        }
        __syncthreads();
#pragma unroll 8
        for (int kk = 0; kk < 32; kk++) {
            unsigned long long a2[4], b2[4];
#pragma unroll
            for (int r = 0; r < 4; r++) a2[r] = dup2(As[kk][ti + 16 * r]);
#pragma unroll
            for (int c = 0; c < 4; c++) b2[c] = *(const unsigned long long*)&Bs[kk][2 * tj + 32 * c];
#pragma unroll
            for (int r = 0; r < 4; r++)
#pragma unroll
                for (int c = 0; c < 4; c++) fma2(acc[r][c], a2[r], b2[c]);
        }
        __syncthreads();
    }
    float bestv[4]; int besti[4];
#pragma unroll
    for (int r = 0; r < 4; r++) { bestv[r] = INFINITY; besti[r] = 0; }
#pragma unroll
    for (int c = 0; c < 4; c++) {
        int n = n0 + 2 * tj + 32 * c;
        float cn0 = g_cnorm[q * NV + n], cn1 = g_cnorm[q * NV + n + 1];
#pragma unroll
        for (int r = 0; r < 4; r++) {
            float2 dv = unpack2(acc[r][c]);
            float s0 = cn0 - 2.0f * dv.x, s1 = cn1 - 2.0f * dv.y;
            if (s0 < bestv[r]) { bestv[r] = s0; besti[r] = n; }
            if (s1 < bestv[r]) { bestv[r] = s1; besti[r] = n + 1; }
        }
    }
#pragma unroll
    for (int r = 0; r < 4; r++) {
        float v = bestv[r]; int ix = besti[r];
        for (int off = 8; off > 0; off >>= 1) {
            float ov = __shfl_down_sync(0xffffffffu, v, off, 16);
            int   oi = __shfl_down_sync(0xffffffffu, ix, off, 16);
            if (ov < v || (ov == v && oi < ix)) { v = ov; ix = oi; }
        }
        if (tj == 0) {
            unsigned u = __float_as_uint(v);
            u = (u & 0x80000000u) ? ~u : (u | 0x80000000u);
            atomicMin(&g_bestkey[m0 + ti + 16 * r], ((unsigned long long)u << 32) | (unsigned)ix);
        }
    }
}

// ---------------- extract idx + histogram (s>=2) ----------------
__global__ void post_quantize_kernel(int s, int slog) {
    int m = blockIdx.x * blockDim.x + threadIdx.x;
    if (m >= NB * s) return;
    int v = (int)(g_bestkey[m] & 0xFFFFFFFFULL);
    int b = m >> slog, j = m & (s - 1);
    g_idxbuf[b * NIDX + (s - 1) + j] = v;
    atomicAdd(&g_counts[v], 1);
}

// ---------------- upsample -> tf32 splits (ci permuted) ----------------
__global__ void upsample_split_kernel(const float* __restrict__ cb, int s) {
    int b = blockIdx.x, t = blockIdx.y;
    float u = (t + 0.5f) * ((float)s / 128.0f) - 0.5f;
    float jf = floorf(u);
    float f = u - jf;
    int j0 = (int)jf, j1 = j0 + 1;
    if (j0 < 0) j0 = 0; if (j0 > s - 1) j0 = s - 1;
    if (j1 < 0) j1 = 0; if (j1 > s - 1) j1 = s - 1;
    int v0 = g_idxbuf[b * NIDX + (s - 1) + j0];
    int v1 = g_idxbuf[b * NIDX + (s - 1) + j1];
    const float* c0 = cb + (long long)v0 * NC;
    const float* c1 = cb + (long long)v1 * NC;
    float w1 = f, w0 = 1.0f - f;
    long long base = ((long long)(b * NT + t)) * NC;
    for (int c = threadIdx.x; c < NC; c += 128) {
        float val = w0 * c0[c] + w1 * c1[c];
        float hi, lo;
        split2(val, hi, lo);
        int cp = pos8(c);
        g_xs_a[base + cp]         = hi;
        g_xs_a[base + cp + PLANE] = lo;
    }
}

// ---------------- tf32 mma conv: both W and X cp.async double-buffered, 1 barrier/chunk ----------------
// smem floats: W 2 bufs * 6*3072 (pitch 24) @0; X 2 bufs * 4*130*20 (pitch 20) @36864.
#define WBUF 18432
#define XOFF 36864
#define XBUF 10400
#define CONV_SMEM ((XOFF + 2*XBUF)*4)   // 230656 B
__global__ __launch_bounds__(512, 1) void conv_tc_kernel(
    const float* __restrict__ xs,   // [2][b][t][ci-permuted]
    const float* __restrict__ wsp,  // [6][co][ci-permuted] for this layer
    const float* __restrict__ bias,
    float* __restrict__ ys,
    const float* __restrict__ z, int fuse)
{
    extern __shared__ float sm[];
    const unsigned sbase = smem_u32(sm);
    const int tid = threadIdx.x, lane = tid & 31, wid = tid >> 5;
    const int h = wid >> 3, wh = wid & 7;
    const int cg = wh >> 2, tg = wh & 3;
    const int b0 = blockIdx.y * 2, co0 = blockIdx.x * 128;
    const int lq = lane >> 2, lr = lane & 3;

    // zero X halo rows (rows 0 and 129 of each (buf, plane)) once
    for (int e = tid; e < 320; e += 512) {
        int w = e % 20, r = e / 20;            // r < 16
        int buf = r >> 3, pl = (r >> 1) & 3, rr = r & 1;
        sm[XOFF + buf * XBUF + pl * 2600 + (rr ? 129 : 0) * 20 + w] = 0.0f;
    }

    float acc[4][4][4];
#pragma unroll
    for (int mt = 0; mt < 4; mt++)
#pragma unroll
        for (int nt = 0; nt < 4; nt++)
#pragma unroll
            for (int r = 0; r < 4; r++) acc[mt][nt][r] = 0.0f;

    // ---- async copy issuers ----
#define ISSUE_W(CI0, BUF) do { \
    _Pragma("unroll") \
    for (int i = 0; i < 6; i++) { \
        int e = tid + 512 * i; \
        int tile = e >> 9, r = e & 511, row = r >> 2, q = r & 3; \
        const float* src = wsp + (long long)tile * (NC * NC) \
                           + (long long)(co0 + row) * NC + (CI0) + q * 4; \
        unsigned dst = sbase + (unsigned)((BUF) * WBUF + tile * 3072 + row * 24 + q * 4) * 4u; \
        asm volatile("cp.async.cg.shared.global [%0], [%1], 16;" :: "r"(dst), "l"(src)); \
    } } while (0)
#define ISSUE_X(CI0, BUF) do { \
    _Pragma("unroll") \
    for (int i = 0; i < 4; i++) { \
        int e = tid + 512 * i; \
        int hb = e >> 10, rem = e & 1023, sp = rem >> 9, r = rem & 511; \
        int row = r >> 2, q = r & 3; \
        const float* src = xs + (long long)sp * PLANE \
                           + ((long long)((b0 + hb) * NT + row)) * NC + (CI0) + q * 4; \
        unsigned dst = sbase + (unsigned)(XOFF + (BUF) * XBUF + (hb * 2 + sp) * 2600 \
                                          + (row + 1) * 20 + q * 4) * 4u; \
        asm volatile("cp.async.cg.shared.global [%0], [%1], 16;" :: "r"(dst), "l"(src)); \
    } } while (0)

    ISSUE_W(0, 0);
    ISSUE_X(0, 0);
    asm volatile("cp.async.commit_group;");

    for (int ch = 0; ch < 32; ch++) {
        const int buf = ch & 1;
        asm volatile("cp.async.wait_group 0;");
        __syncthreads();   // data(ch) visible; MMA(ch-1) done -> buf^1 free

        if (ch < 31) {
            int ci1 = (ch + 1) * 16;
            ISSUE_W(ci1, buf ^ 1);
            ISSUE_X(ci1, buf ^ 1);
            asm volatile("cp.async.commit_group;");
        }

        const float* Wb = sm + buf * WBUF;
        const float* Xb = sm + XOFF + buf * XBUF + h * 5200;   // h*2 planes * 2600
#pragma unroll
        for (int tap = 0; tap < 3; tap++) {
#pragma unroll
            for (int k8 = 0; k8 < 2; k8++) {
                const float* Whi = Wb + tap * 3072;
                const float* Wlo = Wb + (3 + tap) * 3072;
                const float* Xhi = Xb;
                const float* Xlo = Xb + 2600;
                // B fragments (shared across both W splits)
                uint2 bhi[4], blo[4];
#pragma unroll
                for (int nt = 0; nt < 4; nt++) {
                    int trow = tg * 32 + nt * 8 + lq + tap;
                    bhi[nt] = *(const uint2*)&Xhi[trow * 20 + k8 * 8 + lr * 2];
                    blo[nt] = *(const uint2*)&Xlo[trow * 20 + k8 * 8 + lr * 2];
                }
                // A_hi fragments, then 2 MMA passes
                unsigned ahi[4][4];
#pragma unroll
                for (int mt = 0; mt < 4; mt++) {
                    int row = cg * 64 + mt * 16 + lq;
                    uint2 p0 = *(const uint2*)&Whi[row * 24 + k8 * 8 + lr * 2];
                    uint2 p1 = *(const uint2*)&Whi[(row + 8) * 24 + k8 * 8 + lr * 2];
                    ahi[mt][0] = p0.x; ahi[mt][2] = p0.y;
                    ahi[mt][1] = p1.x; ahi[mt][3] = p1.y;
                }
#pragma unroll
                for (int nt = 0; nt < 4; nt++)
#pragma unroll
                    for (int mt = 0; mt < 4; mt++)
                        mma_tf32(acc[mt][nt], ahi[mt], bhi[nt]);
#pragma unroll
                for (int nt = 0; nt < 4; nt++)
#pragma unroll
                    for (int mt = 0; mt < 4; mt++)
                        mma_tf32(acc[mt][nt], ahi[mt], blo[nt]);
                // A_lo fragments, third MMA pass
                unsigned alo[4][4];
#pragma unroll
                for (int mt = 0; mt < 4; mt++) {
                    int row = cg * 64 + mt * 16 + lq;
                    uint2 p0 = *(const uint2*)&Wlo[row * 24 + k8 * 8 + lr * 2];
                    uint2 p1 = *(const uint2*)&Wlo[(row + 8) * 24 + k8 * 8 + lr * 2];
                    alo[mt][0] = p0.x; alo[mt][2] = p0.y;
                    alo[mt][1] = p1.x; alo[mt][3] = p1.y;
                }
#pragma unroll
                for (int nt = 0; nt < 4; nt++)
#pragma unroll
                    for (int mt = 0; mt < 4; mt++)
                        mma_tf32(acc[mt][nt], alo[mt], bhi[nt]);
            }
        }
    }
#undef ISSUE_W
#undef ISSUE_X

    // ---- epilogue ----
    if (!fuse) {
        for (int hb = 0; hb < 2; hb++) {
            __syncthreads();
            if (h == hb) {
#pragma unroll
                for (int mt = 0; mt < 4; mt++)
#pragma unroll
                    for (int nt = 0; nt < 4; nt++) {
                        int row = cg * 64 + mt * 16 + lq;
                        int t0 = tg * 32 + nt * 8 + lr * 2;
                        sm[t0 * 130 + row]           = acc[mt][nt][0];
                        sm[(t0 + 1) * 130 + row]     = acc[mt][nt][1];
                        sm[t0 * 130 + row + 8]       = acc[mt][nt][2];
                        sm[(t0 + 1) * 130 + row + 8] = acc[mt][nt][3];
                    }
            }
            __syncthreads();
            int b = b0 + hb;
            for (int e = tid; e < 16384; e += 512) {
                int t = e >> 7, co = e & 127;
                float v = fmaxf(sm[t * 130 + co] + bias[co0 + co], 0.0f);
                float hi, lo;
                split2(v, hi, lo);
                long long o = ((long long)(b * NT + t)) * NC + co0 + pos8(co);
                ys[o]         = hi;
                ys[o + PLANE] = lo;
            }
        }
    } else {
        float lsum = 0.0f;
        int b = b0 + h;
#pragma unroll
        for (int mt = 0; mt < 4; mt++)
#pragma unroll
            for (int nt = 0; nt < 4; nt++) {
                int row = cg * 64 + mt * 16 + lq;
                int t0 = tg * 32 + nt * 8 + lr * 2;
#pragma unroll
                for (int hh = 0; hh < 2; hh++) {
                    int co = co0 + row + hh * 8;
                    float bv = bias[co];
                    float y0 = fmaxf(acc[mt][nt][hh * 2 + 0] + bv, 0.0f);
                    float y1 = fmaxf(acc[mt][nt][hh * 2 + 1] + bv, 0.0f);
                    long long i = ((long long)(b * NC + co)) * NT + t0;
                    float2 zh  = *(float2*)&g_zhat[i];
                    float2 zz  = *(const float2*)&z[i];
                    float2 zqv = *(float2*)&g_zq[i];
                    zh.x += y0; zh.y += y1;
                    *(float2*)&g_zhat[i] = zh;
                    zqv.x -= y0; zqv.y -= y1;
                    *(float2*)&g_zq[i] = zqv;
                    float d0 = zh.x - zz.x, d1 = zh.y - zz.y;
                    lsum += d0 * d0 + d1 * d1;
                }
            }
        __syncthreads();
        for (int o = 16; o > 0; o >>= 1) lsum += __shfl_down_sync(0xffffffffu, lsum, o);
        if ((tid & 31) == 0) sm[tid >> 5] = lsum;
        __syncthreads();
        if (tid == 0) {
            float s = 0.0f;
#pragma unroll
            for (int i2 = 0; i2 < 16; i2++) s += sm[i2];
            g_partial[blockIdx.y * 4 + blockIdx.x] = s;
        }
    }
}

// ---------------- per-scale finalize ----------------
__global__ void finalize_kernel(int s) {
    __shared__ float sh[32];
    int tid = threadIdx.x;
    float lsum = (tid < 128) ? g_partial[tid] : 0.0f;
    for (int o = 16; o > 0; o >>= 1) lsum += __shfl_down_sync(0xffffffffu, lsum, o);
    if ((tid & 31) == 0) sh[tid >> 5] = lsum;
    __syncthreads();
    float loss_total = 0.0f;
    if (tid == 0) for (int w = 0; w < 32; w++) loss_total += sh[w];
    __syncthreads();
    int c = g_counts[tid];
    float used = (c > 0) ? 1.0f : 0.0f;
    float p = (float)c / (float)(NB * s);
    float ent = p * logf(p + 1e-10f);
    float us = used;
    for (int o = 16; o > 0; o >>= 1) us += __shfl_down_sync(0xffffffffu, us, o);
    if ((tid & 31) == 0) sh[tid >> 5] = us;
    __syncthreads();
    float used_total = 0.0f;
    if (tid == 0) for (int w = 0; w < 32; w++) used_total += sh[w];
    __syncthreads();
    float es = ent;
    for (int o = 16; o > 0; o >>= 1) es += __shfl_down_sync(0xffffffffu, es, o);
    if ((tid & 31) == 0) sh[tid >> 5] = es;
    __syncthreads();
    float ent_total = 0.0f;
    if (tid == 0) for (int w = 0; w < 32; w++) ent_total += sh[w];
    if (tid == 0) {
        g_sums[0] += used_total * (100.0f / (float)NV);
        g_sums[1] += 1.25f * loss_total / (float)NELEM;
        g_sums[2] += expf(-ent_total);
    }
    g_counts[tid] = 0;
    for (int i = tid; i < NB * NT; i += 1024) g_bestkey[i] = ~0ULL;
}

// ---------------- write outputs ----------------
__global__ void writeout_kernel(float* __restrict__ out, int out_size) {
    long long stride = (long long)gridDim.x * blockDim.x;
    long long t0 = (long long)blockIdx.x * blockDim.x + threadIdx.x;
    for (long long i = t0; i < NELEM && i < out_size; i += stride) out[i] = g_zhat[i];
    if (t0 == 0) {
        if (NELEM + 0 < out_size) out[NELEM + 0] = g_sums[0] / 8.0f;
        if (NELEM + 1 < out_size) out[NELEM + 1] = g_sums[1] / 8.0f;
        if (NELEM + 2 < out_size) out[NELEM + 2] = g_sums[2] / 8.0f;
    }
    if (t0 < NB * NIDX && NELEM + 3 + t0 < out_size)
        out[NELEM + 3 + t0] = (float)g_idxbuf[t0];
}

// ---------------- host ----------------
extern "C" void kernel_launch(void* const* d_in, const int* in_sizes, int n_in,
                              void* d_out, int out_size) {
    const float* z  = (const float*)d_in[0];
    const float* cb = (const float*)d_in[1];
    const float* pw = (const float*)d_in[2];
    const float* pb = (const float*)d_in[3];
    float* out = (float*)d_out;

    void *p_xa = 0, *p_xb = 0, *p_w = 0;
    cudaGetSymbolAddress(&p_xa, g_xs_a);
    cudaGetSymbolAddress(&p_xb, g_xs_b);
    cudaGetSymbolAddress(&p_w,  g_wsp);
    cudaFuncSetAttribute(conv_tc_kernel, cudaFuncAttributeMaxDynamicSharedMemorySize, CONV_SMEM);

    mega_init_kernel<<<26624, 256>>>(z, cb, pw);                   // user launch 0

    for (int q = 0; q < NQ; q++) {
        int s = 1 << q, slog = q, M = NB * s;
        const float* cbq = cb + (long long)q * NV * NC;

        if (s == 1) {
            quant_s1_kernel<<<64, 256>>>(cbq);                     // launch 1
        } else if (s <= 4) {
            downsample_warp_kernel<<<(NB * NC * s) / 8, 256>>>(s, slog);
            if (s == 2) quantize_small_kernel<2><<<dim3(64, 8), 256>>>(cbq, q);
            else        quantize_small_kernel<4><<<dim3(64, 8), 256>>>(cbq, q);
            post_quantize_kernel<<<(M + 255) / 256, 256>>>(s, slog);
        } else {
            downsample_kernel<<<(NB * NC * s + 255) / 256, 256>>>(s, slog);
            if (s == 8) quantize_small_kernel<8><<<dim3(64, 8), 256>>>(cbq, q);
            else        quantize_gemm_kernel<<<dim3(M / 64, 8), 256>>>(cbq, q, s, slog);
            post_quantize_kernel<<<(M + 255) / 256, 256>>>(s, slog);
        }

        upsample_split_kernel<<<dim3(NB, NT), 128>>>(cbq, s);      // q=0: launch 2

        const float* w0 = (const float*)p_w + ((long long)q * 2 + 0) * 6 * NC * NC;
        const float* w1 = (const float*)p_w + ((long long)q * 2 + 1) * 6 * NC * NC;
        const float* b0 = pb + ((long long)q * 2 + 0) * NC;
        const float* b1 = pb + ((long long)q * 2 + 1) * NC;
        conv_tc_kernel<<<dim3(4, 32), 512, CONV_SMEM>>>(
            (const float*)p_xa, w0, b0, (float*)p_xb, z, 0);       // q=0: launch 3 <-- ncu -s 5
        conv_tc_kernel<<<dim3(4, 32), 512, CONV_SMEM>>>(
            (const float*)p_xb, w1, b1, (float*)0, z, 1);

        finalize_kernel<<<1, 1024>>>(s);
    }

    writeout_kernel<<<2048, 256>>>(out, out_size);
}